// round 7
// baseline (speedup 1.0000x reference)
#include <cuda_runtime.h>
#include <math.h>

#define NN 8192
#define DD 64
#define CC 100
#define TT 30
#define NPAIR 465      // TT*(TT+1)/2

// ---- device-global scratch ----
__device__ float g_lp[NN * CC];        // lp[n][c]  (transposed for out_kernel)
__device__ float g_G[CC * TT * 32];    // Gram rows pitch 32
__device__ float g_al[CC * 32];
__device__ float g_be[CC * 32];
__device__ float g_n0[CC * 32];

typedef unsigned long long u64;

__device__ __forceinline__ float2 upk2(u64 v) {
    float2 f; asm("mov.b64 {%0, %1}, %2;" : "=f"(f.x), "=f"(f.y) : "l"(v)); return f;
}
__device__ __forceinline__ u64 pk2(float lo, float hi) {
    u64 r; asm("mov.b64 %0, {%1, %2};" : "=l"(r) : "f"(lo), "f"(hi)); return r;
}
__device__ __forceinline__ u64 fma2(u64 a, u64 b, u64 c) {
    u64 d; asm("fma.rn.f32x2 %0, %1, %2, %3;" : "=l"(d) : "l"(a), "l"(b), "l"(c)); return d;
}
__device__ __forceinline__ u64 add2(u64 a, u64 b) {
    u64 d; asm("add.rn.f32x2 %0, %1, %2;" : "=l"(d) : "l"(a), "l"(b)); return d;
}

// ---- prep: per-class params + Gram, conflict-free pitch-65 staging ----
__global__ void __launch_bounds__(512) prep_kernel(const float* __restrict__ z0,
                                                   const float* __restrict__ ap,
                                                   const float* __restrict__ bp) {
    __shared__ float sz[TT * 65];
    const int tid = threadIdx.x;
    const int c = blockIdx.x;

    for (int i = tid; i < TT * DD; i += 512) {
        int r = i >> 6, col = i & 63;
        sz[r * 65 + col] = z0[(size_t)c * TT * DD + i];
    }
    if (tid < TT) {
        float a  = log1pf(__expf(ap[c * TT + tid]));
        float be = log1pf(__expf(bp[c * TT + tid])) - a;
        g_al[c * 32 + tid] = a;
        g_be[c * 32 + tid] = be;
    }
    __syncthreads();

    int k = tid;
    if (k < NPAIR) {
        int t = (int)((__fsqrt_rn(8.f * k + 1.f) - 1.f) * 0.5f);
        while ((t + 1) * (t + 2) / 2 <= k) ++t;
        while (t * (t + 1) / 2 > k) --t;
        int i = k - t * (t + 1) / 2;
        const float* za = sz + t * 65;
        const float* zb = sz + i * 65;
        float a0 = 0.f, a1 = 0.f, a2 = 0.f, a3 = 0.f;
        #pragma unroll
        for (int d = 0; d < DD; d += 4) {
            a0 = fmaf(za[d],     zb[d],     a0);
            a1 = fmaf(za[d + 1], zb[d + 1], a1);
            a2 = fmaf(za[d + 2], zb[d + 2], a2);
            a3 = fmaf(za[d + 3], zb[d + 3], a3);
        }
        float dot = (a0 + a1) + (a2 + a3);
        if (i == t) g_n0[c * 32 + t] = dot;
        else        g_G[(size_t)c * TT * 32 + t * 32 + i] = dot;
    }
}

// ---- flow: block = 128 samples x 1 class; quarter-tile x staging ----
// grid (N/128, C); 5 blocks/SM target
__global__ void __launch_bounds__(128, 5) flow_kernel(const float* __restrict__ x,
                                                      const float* __restrict__ z0g) {
    __shared__ __align__(16) float sz0[TT * DD];     // 7680 B
    __shared__ __align__(16) float sG[TT * 32];      // 3840 B
    __shared__ float sal[32], sbe[32], sn0[32];
    __shared__ __align__(16) float sxt[32 * 68];     // 8704 B (quarter tile)
    __shared__ __align__(16) float sp[TT * 128];     // 15360 B
                                                     // total ~36.0 KB

    const int tid = threadIdx.x;
    const int c = blockIdx.y;
    const int nbase = blockIdx.x * 128;

    // stage z0 + G + params
    {
        const float4* gz = (const float4*)(z0g + (size_t)c * TT * DD);
        float4* s4 = (float4*)sz0;
        #pragma unroll
        for (int i = tid; i < 480; i += 128) s4[i] = gz[i];
    }
    {
        const float4* gg = (const float4*)(g_G + (size_t)c * TT * 32);
        float4* s4 = (float4*)sG;
        #pragma unroll
        for (int i = tid; i < 240; i += 128) s4[i] = gg[i];
    }
    if (tid < TT) {
        sal[tid] = g_al[c * 32 + tid];
        sbe[tid] = g_be[c * 32 + tid];
        sn0[tid] = g_n0[c * 32 + tid];
    }

    u64 xv[32];
    float4* sx4 = (float4*)sxt;

    // ---- quarter-tile x staging: 4 passes of 32 rows ----
    #pragma unroll
    for (int pass = 0; pass < 4; ++pass) {
        const float4* gx = (const float4*)(x + (size_t)(nbase + 32 * pass) * DD);
        __syncthreads();
        #pragma unroll
        for (int it = 0; it < 4; ++it) {
            int idx = tid + 128 * it;              // 512 float4 per pass
            int r = idx >> 4, col = idx & 15;
            sx4[r * 17 + col] = gx[idx];
        }
        __syncthreads();
        if ((tid >> 5) == pass) {
            const ulonglong2* xr = (const ulonglong2*)(sxt + (tid & 31) * 68);
            #pragma unroll
            for (int j = 0; j < 16; ++j) {
                ulonglong2 v = xr[j];
                xv[2 * j] = v.x; xv[2 * j + 1] = v.y;
            }
        }
    }

    // q0 = ||x||^2
    float q0;
    {
        u64 a0 = 0ull, a1 = 0ull, a2 = 0ull, a3 = 0ull;
        #pragma unroll
        for (int j = 0; j < 32; j += 4) {
            a0 = fma2(xv[j],     xv[j],     a0);
            a1 = fma2(xv[j + 1], xv[j + 1], a1);
            a2 = fma2(xv[j + 2], xv[j + 2], a2);
            a3 = fma2(xv[j + 3], xv[j + 3], a3);
        }
        float2 f = upk2(add2(add2(a0, a1), add2(a2, a3)));
        q0 = f.x + f.y;
    }

    // ---- P phase: p[t] = x . z0[t]  (z0 broadcast) ----
    #pragma unroll 1
    for (int t = 0; t < TT; ++t) {
        const ulonglong2* zp = (const ulonglong2*)(sz0 + t * DD);
        u64 a0 = 0ull, a1 = 0ull, a2 = 0ull, a3 = 0ull;
        #pragma unroll
        for (int j = 0; j < 16; j += 2) {
            ulonglong2 v0 = zp[j], v1 = zp[j + 1];
            a0 = fma2(xv[2 * j],     v0.x, a0);
            a1 = fma2(xv[2 * j + 1], v0.y, a1);
            a2 = fma2(xv[2 * j + 2], v1.x, a2);
            a3 = fma2(xv[2 * j + 3], v1.y, a3);
        }
        float2 f = upk2(add2(add2(a0, a1), add2(a2, a3)));
        sp[t * 128 + tid] = f.x + f.y;   // own slot; no sync needed
    }

    // ---- scalar chain: packed-pair Gram dot, log-free accumulation ----
    u64 wp[TT / 2];        // packed pairs {w[2k], w[2k+1]}
    float w_pend = 0.f;    // pending even-index w
    float g = 1.f, gi = 1.f, q = q0, prod = 1.f;

    #pragma unroll
    for (int t = 0; t < TT; ++t) {
        float base = sp[t * 128 + tid];
        const int npair = t >> 1;
        u64 acc0 = 0ull, acc1 = 0ull;
        const u64* Gp = (const u64*)(sG + t * 32);
        int k = 0;
        #pragma unroll
        for (; k + 2 <= npair; k += 2) {
            ulonglong2 gq = *(const ulonglong2*)(Gp + k);
            acc0 = fma2(wp[k],     gq.x, acc0);
            acc1 = fma2(wp[k + 1], gq.y, acc1);
        }
        #pragma unroll
        for (; k < npair; ++k) acc0 = fma2(wp[k], Gp[k], acc0);
        float2 f = upk2(add2(acc0, acc1));
        float dot = base + f.x + f.y;
        if (t & 1) dot = fmaf(w_pend, ((const float*)Gp)[t - 1], dot);
        float s = g * dot;

        float al = sal[t], be = sbe[t], nn = sn0[t];
        float r2 = fmaxf(fmaf(-2.f, s, q) + nn, 1e-20f);
        float rin = rsqrtf(r2);
        float r = r2 * rin;
        float den = al + r;
        float h = __frcp_rn(den);
        float v = __frcp_rn(den + be);
        float bh = be * h;
        float opbh = 1.f + bh;
        float t2 = opbh - bh * (h * r);
        prod *= t2;
        q = fmaf(bh * bh, r2, fmaf(2.f * bh, q - s, q));
        g *= opbh;
        gi *= den * v;                   // gi = 1/g
        float wt = -bh * gi;
        if (t & 1) wp[t >> 1] = pk2(w_pend, wt);
        else       w_pend = wt;
    }

    float lp = 63.f * __logf(g) + __logf(prod) - 0.5f * q - 58.8120661251f;
    g_lp[(size_t)(nbase + tid) * CC + c] = lp;
}

// ---- epilogue: warp = sample; 16 samples per block ----
__global__ void __launch_bounds__(512) out_kernel(const float* __restrict__ x,
                                                  const int* __restrict__ labels,
                                                  const float* __restrict__ freq,
                                                  const float* __restrict__ W,
                                                  const float* __restrict__ b,
                                                  float* __restrict__ out) {
    __shared__ __align__(16) float sWt[CC * 68];
    __shared__ __align__(16) float sxr[16 * 68];
    __shared__ float sb[CC], slf[CC];
    const int tid = threadIdx.x;
    for (int i = tid; i < DD * CC; i += 512) {
        int d = i / CC, cc = i % CC;
        sWt[cc * 68 + d] = W[i];
    }
    for (int i = tid; i < CC; i += 512) { sb[i] = b[i]; slf[i] = __logf(freq[i]); }

    const int wid = tid >> 5, lane = tid & 31;
    const int n = blockIdx.x * 16 + wid;
    {
        const float2* xp = (const float2*)(x + (size_t)n * DD);
        ((float2*)(sxr + wid * 68))[lane] = xp[lane];
    }
    __syncthreads();

    u64 xv[32];
    {
        const ulonglong2* xr = (const ulonglong2*)(sxr + wid * 68);
        #pragma unroll
        for (int j = 0; j < 16; ++j) {
            ulonglong2 v = xr[j];
            xv[2 * j] = v.x; xv[2 * j + 1] = v.y;
        }
    }

    const float* lprow = g_lp + (size_t)n * CC;
    float lg[4], lq[4];
    float mlg = -1e30f, mlp = -1e30f;
    #pragma unroll
    for (int k = 0; k < 4; ++k) {
        int cc = lane + 32 * k;
        if (cc < CC) {
            const ulonglong2* wr = (const ulonglong2*)(sWt + cc * 68);
            u64 a0 = 0ull, a1 = 0ull;
            #pragma unroll
            for (int j = 0; j < 16; ++j) {
                ulonglong2 v = wr[j];
                a0 = fma2(xv[2 * j],     v.x, a0);
                a1 = fma2(xv[2 * j + 1], v.y, a1);
            }
            float2 f = upk2(add2(a0, a1));
            lg[k] = f.x + f.y + sb[cc];
            lq[k] = lprow[cc] + slf[cc];
        } else {
            lg[k] = -1e30f; lq[k] = -1e30f;
        }
        mlg = fmaxf(mlg, lg[k]);
        mlp = fmaxf(mlp, lq[k]);
    }
    #pragma unroll
    for (int o = 16; o; o >>= 1) {
        mlg = fmaxf(mlg, __shfl_xor_sync(0xffffffffu, mlg, o));
        mlp = fmaxf(mlp, __shfl_xor_sync(0xffffffffu, mlp, o));
    }
    float se = 0.f, sl = 0.f;
    #pragma unroll
    for (int k = 0; k < 4; ++k) {
        if (lane + 32 * k < CC) {
            se += __expf(lq[k] - mlp);
            sl += __expf(lg[k] - mlg);
        }
    }
    #pragma unroll
    for (int o = 16; o; o >>= 1) {
        se += __shfl_xor_sync(0xffffffffu, se, o);
        sl += __shfl_xor_sync(0xffffffffu, sl, o);
    }
    float marg = mlp + __logf(se);
    float logev = fminf(marg + 80.992775903f, 10.f);
    float E = __expf(logev) / sl;

    float* o = out + (size_t)n * (CC + 1);
    #pragma unroll
    for (int k = 0; k < 4; ++k) {
        int cc = lane + 32 * k;
        if (cc < CC)
            o[cc] = __logf(fmaf(E, __expf(lg[k] - mlg), 1.f));
    }
    if (lane == 0)
        o[CC] = lprow[labels[n]];
}

extern "C" void kernel_launch(void* const* d_in, const int* in_sizes, int n_in,
                              void* d_out, int out_size) {
    const float* x      = (const float*)d_in[0];
    const int*   labels = (const int*)d_in[1];
    const float* freq   = (const float*)d_in[2];
    const float* z0     = (const float*)d_in[3];
    const float* ap     = (const float*)d_in[4];
    const float* bp     = (const float*)d_in[5];
    const float* W      = (const float*)d_in[6];
    const float* b      = (const float*)d_in[7];
    float* out = (float*)d_out;

    prep_kernel<<<CC, 512>>>(z0, ap, bp);
    dim3 grid(NN / 128, CC);
    flow_kernel<<<grid, 128>>>(x, z0);
    out_kernel<<<NN / 16, 512>>>(x, labels, freq, W, b, out);
}

// round 8
// speedup vs baseline: 1.0094x; 1.0094x over previous
#include <cuda_runtime.h>
#include <math.h>

#define NN 8192
#define DD 64
#define CC 100
#define TT 30
#define NPAIR 465      // TT*(TT+1)/2

// ---- device-global scratch ----
__device__ float g_lp[NN * CC];        // lp[n][c]
__device__ float g_G[CC * TT * 32];    // Gram rows pitch 32
__device__ float g_al[CC * 32];
__device__ float g_be[CC * 32];
__device__ float g_n0[CC * 32];

typedef unsigned long long u64;

__device__ __forceinline__ float2 upk2(u64 v) {
    float2 f; asm("mov.b64 {%0, %1}, %2;" : "=f"(f.x), "=f"(f.y) : "l"(v)); return f;
}
__device__ __forceinline__ u64 pk2(float lo, float hi) {
    u64 r; asm("mov.b64 %0, {%1, %2};" : "=l"(r) : "f"(lo), "f"(hi)); return r;
}
__device__ __forceinline__ u64 fma2(u64 a, u64 b, u64 c) {
    u64 d; asm("fma.rn.f32x2 %0, %1, %2, %3;" : "=l"(d) : "l"(a), "l"(b), "l"(c)); return d;
}
__device__ __forceinline__ u64 add2(u64 a, u64 b) {
    u64 d; asm("add.rn.f32x2 %0, %1, %2;" : "=l"(d) : "l"(a), "l"(b)); return d;
}

// ---- prep: per-class params + Gram, conflict-free pitch-65 staging ----
__global__ void __launch_bounds__(512) prep_kernel(const float* __restrict__ z0,
                                                   const float* __restrict__ ap,
                                                   const float* __restrict__ bp) {
    __shared__ float sz[TT * 65];
    const int tid = threadIdx.x;
    const int c = blockIdx.x;

    for (int i = tid; i < TT * DD; i += 512) {
        int r = i >> 6, col = i & 63;
        sz[r * 65 + col] = z0[(size_t)c * TT * DD + i];
    }
    if (tid < TT) {
        float a  = log1pf(__expf(ap[c * TT + tid]));
        float be = log1pf(__expf(bp[c * TT + tid])) - a;
        g_al[c * 32 + tid] = a;
        g_be[c * 32 + tid] = be;
    }
    __syncthreads();

    int k = tid;
    if (k < NPAIR) {
        int t = (int)((__fsqrt_rn(8.f * k + 1.f) - 1.f) * 0.5f);
        while ((t + 1) * (t + 2) / 2 <= k) ++t;
        while (t * (t + 1) / 2 > k) --t;
        int i = k - t * (t + 1) / 2;
        const float* za = sz + t * 65;
        const float* zb = sz + i * 65;
        float a0 = 0.f, a1 = 0.f, a2 = 0.f, a3 = 0.f;
        #pragma unroll
        for (int d = 0; d < DD; d += 4) {
            a0 = fmaf(za[d],     zb[d],     a0);
            a1 = fmaf(za[d + 1], zb[d + 1], a1);
            a2 = fmaf(za[d + 2], zb[d + 2], a2);
            a3 = fmaf(za[d + 3], zb[d + 3], a3);
        }
        float dot = (a0 + a1) + (a2 + a3);
        if (i == t) g_n0[c * 32 + t] = dot;
        else        g_G[(size_t)c * TT * 32 + t * 32 + i] = dot;
    }
}

// dynamic smem layout (float indices):
//  sz0  [0, 1920)       z0 tile
//  sG2  [1920, 3840)    splatted Gram (960 u64)
//  sprm [3840, 3936)    al/be/n0
//  sxt  [3936, 6112)    32x68 staging quarter-tile
//  sp   [6112, 13792)   P results, interleaved pairs (30 x 128 u64)
#define OFF_Z0  0
#define OFF_G2  1920
#define OFF_PRM 3840
#define OFF_SX  3936
#define OFF_SP  6112
#define SMEM_BYTES (13792 * 4)

// ---- flow: block = 256 samples x 1 class; thread = 2 lane-packed chains ----
// grid (NN/256, CC)
__global__ void __launch_bounds__(128, 4) flow_kernel(const float* __restrict__ x,
                                                      const float* __restrict__ z0g) {
    extern __shared__ __align__(16) float sm[];
    float* sz0 = sm + OFF_Z0;
    u64*   sG2 = (u64*)(sm + OFF_G2);
    float* sal = sm + OFF_PRM;
    float* sbe = sm + OFF_PRM + 32;
    float* sn0 = sm + OFF_PRM + 64;
    float* sxt = sm + OFF_SX;
    float* spf = sm + OFF_SP;
    u64*   spq = (u64*)(sm + OFF_SP);

    const int tid = threadIdx.x;
    const int c = blockIdx.y;
    const int nbase = blockIdx.x * 256;

    // stage z0
    {
        const float4* gz = (const float4*)(z0g + (size_t)c * TT * DD);
        float4* s4 = (float4*)sz0;
        #pragma unroll
        for (int i = tid; i < 480; i += 128) s4[i] = gz[i];
    }
    // stage splatted Gram
    {
        const float* gg = g_G + (size_t)c * TT * 32;
        #pragma unroll
        for (int k = tid; k < 960; k += 128) {
            float v = gg[k];
            sG2[k] = pk2(v, v);
        }
    }
    if (tid < TT) {
        sal[tid] = g_al[c * 32 + tid];
        sbe[tid] = g_be[c * 32 + tid];
        sn0[tid] = g_n0[c * 32 + tid];
    }

    float qh[2];
    float4* sx4 = (float4*)sxt;

    #pragma unroll
    for (int half = 0; half < 2; ++half) {
        u64 xv[32];
        // quarter-tile staging: 4 passes of 32 rows
        #pragma unroll
        for (int pass = 0; pass < 4; ++pass) {
            const float4* gx = (const float4*)(x + (size_t)(nbase + half * 128 + 32 * pass) * DD);
            __syncthreads();
            #pragma unroll
            for (int it = 0; it < 4; ++it) {
                int idx = tid + 128 * it;
                int r = idx >> 4, col = idx & 15;
                sx4[r * 17 + col] = gx[idx];
            }
            __syncthreads();
            if ((tid >> 5) == pass) {
                const ulonglong2* xr = (const ulonglong2*)(sxt + (tid & 31) * 68);
                #pragma unroll
                for (int j = 0; j < 16; ++j) {
                    ulonglong2 v = xr[j];
                    xv[2 * j] = v.x; xv[2 * j + 1] = v.y;
                }
            }
        }
        // q = ||x||^2
        {
            u64 a0 = 0ull, a1 = 0ull, a2 = 0ull, a3 = 0ull;
            #pragma unroll
            for (int j = 0; j < 32; j += 4) {
                a0 = fma2(xv[j],     xv[j],     a0);
                a1 = fma2(xv[j + 1], xv[j + 1], a1);
                a2 = fma2(xv[j + 2], xv[j + 2], a2);
                a3 = fma2(xv[j + 3], xv[j + 3], a3);
            }
            float2 f = upk2(add2(add2(a0, a1), add2(a2, a3)));
            qh[half] = f.x + f.y;
        }
        // P: p[t] = x . z0[t]
        #pragma unroll 1
        for (int t = 0; t < TT; ++t) {
            const ulonglong2* zp = (const ulonglong2*)(sz0 + t * DD);
            u64 a0 = 0ull, a1 = 0ull, a2 = 0ull, a3 = 0ull;
            #pragma unroll
            for (int j = 0; j < 16; j += 2) {
                ulonglong2 v0 = zp[j], v1 = zp[j + 1];
                a0 = fma2(xv[2 * j],     v0.x, a0);
                a1 = fma2(xv[2 * j + 1], v0.y, a1);
                a2 = fma2(xv[2 * j + 2], v1.x, a2);
                a3 = fma2(xv[2 * j + 3], v1.y, a3);
            }
            float2 f = upk2(add2(add2(a0, a1), add2(a2, a3)));
            spf[t * 256 + 2 * tid + half] = f.x + f.y;   // own slot
        }
    }

    // ---- dual lane-packed chain: samples (nbase+tid) and (nbase+128+tid) ----
    u64 wp[TT];                    // packed {wA[t], wB[t]}
    float qA = qh[0], qB = qh[1];
    float gA = 1.f, gB = 1.f, giA = 1.f, giB = 1.f, prodA = 1.f, prodB = 1.f;

    #pragma unroll
    for (int t = 0; t < TT; ++t) {
        const u64* G2 = sG2 + t * 32;
        u64 acc0 = 0ull, acc1 = 0ull;
        int i = 0;
        #pragma unroll
        for (; i + 2 <= t; i += 2) {
            ulonglong2 gq = *(const ulonglong2*)(G2 + i);
            acc0 = fma2(wp[i],     gq.x, acc0);
            acc1 = fma2(wp[i + 1], gq.y, acc1);
        }
        if (i < t) acc0 = fma2(wp[i], G2[i], acc0);
        float2 dot = upk2(add2(add2(acc0, acc1), spq[t * 128 + tid]));

        float sA = gA * dot.x;
        float sB = gB * dot.y;

        float al = sal[t], be = sbe[t], nn = sn0[t];

        float r2A = fmaxf(fmaf(-2.f, sA, qA) + nn, 1e-20f);
        float r2B = fmaxf(fmaf(-2.f, sB, qB) + nn, 1e-20f);
        float rinA = rsqrtf(r2A), rinB = rsqrtf(r2B);
        float rA = r2A * rinA,    rB = r2B * rinB;
        float denA = al + rA,     denB = al + rB;
        float hA = __frcp_rn(denA),        hB = __frcp_rn(denB);
        float vA = __frcp_rn(denA + be),   vB = __frcp_rn(denB + be);
        float bhA = be * hA,      bhB = be * hB;
        float opA = 1.f + bhA,    opB = 1.f + bhB;
        float t2A = opA - bhA * (hA * rA);
        float t2B = opB - bhB * (hB * rB);
        prodA *= t2A;             prodB *= t2B;
        qA = fmaf(bhA * bhA, r2A, fmaf(2.f * bhA, qA - sA, qA));
        qB = fmaf(bhB * bhB, r2B, fmaf(2.f * bhB, qB - sB, qB));
        gA *= opA;                gB *= opB;
        giA *= denA * vA;         giB *= denB * vB;
        wp[t] = pk2(-bhA * giA, -bhB * giB);
    }

    float lpA = 63.f * __logf(gA) + __logf(prodA) - 0.5f * qA - 58.8120661251f;
    float lpB = 63.f * __logf(gB) + __logf(prodB) - 0.5f * qB - 58.8120661251f;
    g_lp[(size_t)(nbase + tid) * CC + c] = lpA;
    g_lp[(size_t)(nbase + 128 + tid) * CC + c] = lpB;
}

// ---- epilogue: warp = sample; 16 samples per block ----
__global__ void __launch_bounds__(512) out_kernel(const float* __restrict__ x,
                                                  const int* __restrict__ labels,
                                                  const float* __restrict__ freq,
                                                  const float* __restrict__ W,
                                                  const float* __restrict__ b,
                                                  float* __restrict__ out) {
    __shared__ __align__(16) float sWt[CC * 68];
    __shared__ __align__(16) float sxr[16 * 68];
    __shared__ float sb[CC], slf[CC];
    const int tid = threadIdx.x;
    for (int i = tid; i < DD * CC; i += 512) {
        int d = i / CC, cc = i % CC;
        sWt[cc * 68 + d] = W[i];
    }
    for (int i = tid; i < CC; i += 512) { sb[i] = b[i]; slf[i] = __logf(freq[i]); }

    const int wid = tid >> 5, lane = tid & 31;
    const int n = blockIdx.x * 16 + wid;
    {
        const float2* xp = (const float2*)(x + (size_t)n * DD);
        ((float2*)(sxr + wid * 68))[lane] = xp[lane];
    }
    __syncthreads();

    u64 xv[32];
    {
        const ulonglong2* xr = (const ulonglong2*)(sxr + wid * 68);
        #pragma unroll
        for (int j = 0; j < 16; ++j) {
            ulonglong2 v = xr[j];
            xv[2 * j] = v.x; xv[2 * j + 1] = v.y;
        }
    }

    const float* lprow = g_lp + (size_t)n * CC;
    float lg[4], lq[4];
    float mlg = -1e30f, mlp = -1e30f;
    #pragma unroll
    for (int k = 0; k < 4; ++k) {
        int cc = lane + 32 * k;
        if (cc < CC) {
            const ulonglong2* wr = (const ulonglong2*)(sWt + cc * 68);
            u64 a0 = 0ull, a1 = 0ull;
            #pragma unroll
            for (int j = 0; j < 16; ++j) {
                ulonglong2 v = wr[j];
                a0 = fma2(xv[2 * j],     v.x, a0);
                a1 = fma2(xv[2 * j + 1], v.y, a1);
            }
            float2 f = upk2(add2(a0, a1));
            lg[k] = f.x + f.y + sb[cc];
            lq[k] = lprow[cc] + slf[cc];
        } else {
            lg[k] = -1e30f; lq[k] = -1e30f;
        }
        mlg = fmaxf(mlg, lg[k]);
        mlp = fmaxf(mlp, lq[k]);
    }
    #pragma unroll
    for (int o = 16; o; o >>= 1) {
        mlg = fmaxf(mlg, __shfl_xor_sync(0xffffffffu, mlg, o));
        mlp = fmaxf(mlp, __shfl_xor_sync(0xffffffffu, mlp, o));
    }
    float se = 0.f, sl = 0.f;
    #pragma unroll
    for (int k = 0; k < 4; ++k) {
        if (lane + 32 * k < CC) {
            se += __expf(lq[k] - mlp);
            sl += __expf(lg[k] - mlg);
        }
    }
    #pragma unroll
    for (int o = 16; o; o >>= 1) {
        se += __shfl_xor_sync(0xffffffffu, se, o);
        sl += __shfl_xor_sync(0xffffffffu, sl, o);
    }
    float marg = mlp + __logf(se);
    float logev = fminf(marg + 80.992775903f, 10.f);
    float E = __expf(logev) / sl;

    float* o = out + (size_t)n * (CC + 1);
    #pragma unroll
    for (int k = 0; k < 4; ++k) {
        int cc = lane + 32 * k;
        if (cc < CC)
            o[cc] = __logf(fmaf(E, __expf(lg[k] - mlg), 1.f));
    }
    if (lane == 0)
        o[CC] = lprow[labels[n]];
}

extern "C" void kernel_launch(void* const* d_in, const int* in_sizes, int n_in,
                              void* d_out, int out_size) {
    const float* x      = (const float*)d_in[0];
    const int*   labels = (const int*)d_in[1];
    const float* freq   = (const float*)d_in[2];
    const float* z0     = (const float*)d_in[3];
    const float* ap     = (const float*)d_in[4];
    const float* bp     = (const float*)d_in[5];
    const float* W      = (const float*)d_in[6];
    const float* b      = (const float*)d_in[7];
    float* out = (float*)d_out;

    cudaFuncSetAttribute(flow_kernel, cudaFuncAttributeMaxDynamicSharedMemorySize, SMEM_BYTES);

    prep_kernel<<<CC, 512>>>(z0, ap, bp);
    dim3 grid(NN / 256, CC);
    flow_kernel<<<grid, 128, SMEM_BYTES>>>(x, z0);
    out_kernel<<<NN / 16, 512>>>(x, labels, freq, W, b, out);
}

// round 10
// speedup vs baseline: 1.4048x; 1.3917x over previous
#include <cuda_runtime.h>
#include <math.h>
#include <stdint.h>

#define NN 8192
#define DD 64
#define CC 100
#define TT 30
#define NPAIR 465

// ---- device-global scratch ----
__device__ float g_lp[NN * CC];
__device__ float g_G[CC * TT * 32];
__device__ float g_al[CC * 32];
__device__ float g_be[CC * 32];
__device__ float g_n0[CC * 32];

typedef unsigned long long u64;

__device__ __forceinline__ float2 upk2(u64 v) {
    float2 f; asm("mov.b64 {%0, %1}, %2;" : "=f"(f.x), "=f"(f.y) : "l"(v)); return f;
}
__device__ __forceinline__ u64 fma2(u64 a, u64 b, u64 c) {
    u64 d; asm("fma.rn.f32x2 %0, %1, %2, %3;" : "=l"(d) : "l"(a), "l"(b), "l"(c)); return d;
}
__device__ __forceinline__ u64 add2(u64 a, u64 b) {
    u64 d; asm("add.rn.f32x2 %0, %1, %2;" : "=l"(d) : "l"(a), "l"(b)); return d;
}

// ---- prep: per-class params + Gram (proven) ----
__global__ void __launch_bounds__(512) prep_kernel(const float* __restrict__ z0,
                                                   const float* __restrict__ ap,
                                                   const float* __restrict__ bp) {
    __shared__ float sz[TT * 65];
    const int tid = threadIdx.x;
    const int c = blockIdx.x;

    for (int i = tid; i < TT * DD; i += 512) {
        int r = i >> 6, col = i & 63;
        sz[r * 65 + col] = z0[(size_t)c * TT * DD + i];
    }
    if (tid < TT) {
        float a  = log1pf(__expf(ap[c * TT + tid]));
        float be = log1pf(__expf(bp[c * TT + tid])) - a;
        g_al[c * 32 + tid] = a;
        g_be[c * 32 + tid] = be;
    }
    __syncthreads();

    int k = tid;
    if (k < NPAIR) {
        int t = (int)((__fsqrt_rn(8.f * k + 1.f) - 1.f) * 0.5f);
        while ((t + 1) * (t + 2) / 2 <= k) ++t;
        while (t * (t + 1) / 2 > k) --t;
        int i = k - t * (t + 1) / 2;
        const float* za = sz + t * 65;
        const float* zb = sz + i * 65;
        float a0 = 0.f, a1 = 0.f, a2 = 0.f, a3 = 0.f;
        #pragma unroll
        for (int d = 0; d < DD; d += 4) {
            a0 = fmaf(za[d],     zb[d],     a0);
            a1 = fmaf(za[d + 1], zb[d + 1], a1);
            a2 = fmaf(za[d + 2], zb[d + 2], a2);
            a3 = fmaf(za[d + 3], zb[d + 3], a3);
        }
        float dot = (a0 + a1) + (a2 + a3);
        if (i == t) g_n0[c * 32 + t] = dot;
        else        g_G[(size_t)c * TT * 32 + t * 32 + i] = dot;
    }
}

// tf32 warp MMA: D(16x8) += A(16x8) * B(8x8),  row.col
__device__ __forceinline__ void mma_tf32(float& c0, float& c1, float& c2, float& c3,
                                         uint32_t a0, uint32_t a1, uint32_t a2, uint32_t a3,
                                         uint32_t b0, uint32_t b1) {
    asm volatile(
        "mma.sync.aligned.m16n8k8.row.col.f32.tf32.tf32.f32 "
        "{%0,%1,%2,%3}, {%4,%5,%6,%7}, {%8,%9}, {%0,%1,%2,%3};"
        : "+f"(c0), "+f"(c1), "+f"(c2), "+f"(c3)
        : "r"(a0), "r"(a1), "r"(a2), "r"(a3), "r"(b0), "r"(b1));
}

// smem float layout:
//  sx  [0, 8704)        x tile 128 rows x pitch 68  (34816 B); aliased by sp (128 x 33) after P
//  sz  [8704, 10880)    z0 tile 32 rows x pitch 68
//  sG  [10880, 11840)   Gram 30 x 32
//  sprm[11840, 11936)   al/be/n0
#define OFF_SZ  8704
#define OFF_G   10880
#define OFF_PRM 11840
#define SMEM_FLOATS 11936

// ---- flow: block = 128 samples x 1 class; tf32 mma P phase + scalar chain ----
__global__ void __launch_bounds__(128) flow_kernel(const float* __restrict__ x,
                                                   const float* __restrict__ z0g) {
    __shared__ __align__(16) float sm[SMEM_FLOATS];
    float* sx  = sm;
    float* sz  = sm + OFF_SZ;
    float* sG  = sm + OFF_G;
    float* sal = sm + OFF_PRM;
    float* sbe = sm + OFF_PRM + 32;
    float* sn0 = sm + OFF_PRM + 64;

    const int tid = threadIdx.x;
    const int wid = tid >> 5;
    const int lane = tid & 31;
    const int g = lane >> 2;      // group id 0..7
    const int cc4 = lane & 3;     // thread-in-group 0..3
    const int c = blockIdx.y;
    const int nbase = blockIdx.x * 128;

    // stage x tile: coalesced float4, pitch 17 float4 (= 68 floats)
    {
        const float4* gx = (const float4*)(x + (size_t)nbase * DD);
        float4* s4 = (float4*)sx;
        #pragma unroll
        for (int j = 0; j < 16; ++j) {
            int idx = tid + 128 * j;
            int r = idx >> 4, col = idx & 15;
            s4[r * 17 + col] = gx[idx];
        }
    }
    // stage z0 tile: 32 rows x pitch 68, rows 30/31 zero
    {
        const float* gz = z0g + (size_t)c * TT * DD;
        #pragma unroll
        for (int i = tid; i < 2048; i += 128) {
            int r = i >> 6, col = i & 63;
            sz[r * 68 + col] = (i < 1920) ? gz[i] : 0.f;
        }
    }
    // stage Gram + params
    {
        const float4* gg = (const float4*)(g_G + (size_t)c * TT * 32);
        float4* s4 = (float4*)sG;
        #pragma unroll
        for (int i = tid; i < 240; i += 128) s4[i] = gg[i];
    }
    if (tid < TT) {
        sal[tid] = g_al[c * 32 + tid];
        sbe[tid] = g_be[c * 32 + tid];
        sn0[tid] = g_n0[c * 32 + tid];
    }
    __syncthreads();

    // q0 = ||x||^2 from own row (proven R2 pattern)
    float q0;
    {
        const float4* xr = ((const float4*)sx) + tid * 17;
        float a0 = 0.f, a1 = 0.f, a2 = 0.f, a3 = 0.f;
        #pragma unroll
        for (int j = 0; j < 16; ++j) {
            float4 v = xr[j];
            a0 = fmaf(v.x, v.x, a0);
            a1 = fmaf(v.y, v.y, a1);
            a2 = fmaf(v.z, v.z, a2);
            a3 = fmaf(v.w, v.w, a3);
        }
        q0 = (a0 + a1) + (a2 + a3);
    }

    // ---- P phase: warp computes P[32 samples x 32 ts] via tf32 mma ----
    float C[2][4][4];
    #pragma unroll
    for (int mt = 0; mt < 2; ++mt)
        #pragma unroll
        for (int nt = 0; nt < 4; ++nt)
            #pragma unroll
            for (int r = 0; r < 4; ++r) C[mt][nt][r] = 0.f;

    const uint32_t* xa = (const uint32_t*)(sx + (32 * wid + g) * 68);   // A row g (mt0)
    const uint32_t* zb = (const uint32_t*)(sz + g * 68);                // B col g (nt0)

    #pragma unroll
    for (int ks = 0; ks < 8; ++ks) {
        int k0 = 8 * ks + cc4;
        // A fragments: mt0 rows {g, g+8}, mt1 rows {g+16, g+24}; cols {k0, k0+4}
        uint32_t a00 = xa[k0],            a01 = xa[8 * 68 + k0];
        uint32_t a02 = xa[k0 + 4],        a03 = xa[8 * 68 + k0 + 4];
        uint32_t a10 = xa[16 * 68 + k0],  a11 = xa[24 * 68 + k0];
        uint32_t a12 = xa[16 * 68 + k0 + 4], a13 = xa[24 * 68 + k0 + 4];
        // B fragments: nt cols {nt*8+g}, rows {k0, k0+4}
        #pragma unroll
        for (int nt = 0; nt < 4; ++nt) {
            uint32_t b0 = zb[nt * 8 * 68 + k0];
            uint32_t b1 = zb[nt * 8 * 68 + k0 + 4];
            mma_tf32(C[0][nt][0], C[0][nt][1], C[0][nt][2], C[0][nt][3],
                     a00, a01, a02, a03, b0, b1);
            mma_tf32(C[1][nt][0], C[1][nt][1], C[1][nt][2], C[1][nt][3],
                     a10, a11, a12, a13, b0, b1);
        }
    }
    __syncthreads();   // all warps done reading x tile -> alias sp over it

    // write P to sp[s * 33 + t]
    float* sp = sx;
    #pragma unroll
    for (int mt = 0; mt < 2; ++mt) {
        #pragma unroll
        for (int nt = 0; nt < 4; ++nt) {
            int s0 = 32 * wid + mt * 16 + g;
            int t0 = nt * 8 + 2 * cc4;
            sp[s0 * 33 + t0]           = C[mt][nt][0];
            sp[s0 * 33 + t0 + 1]       = C[mt][nt][1];
            sp[(s0 + 8) * 33 + t0]     = C[mt][nt][2];
            sp[(s0 + 8) * 33 + t0 + 1] = C[mt][nt][3];
        }
    }
    __syncwarp();

    // ---- scalar chain (R6 math) ----
    const float* myp = sp + tid * 33;
    float w[TT];
    float gg = 1.f, gi = 1.f, q = q0, prod = 1.f;
    #pragma unroll
    for (int t = 0; t < TT; ++t) {
        float acc0 = myp[t];
        float acc1 = 0.f;
        const float* Gr = sG + t * 32;
        int i = 0;
        #pragma unroll
        for (; i + 4 <= t; i += 4) {
            float4 g4 = *(const float4*)(Gr + i);
            acc0 = fmaf(w[i],     g4.x, acc0);
            acc1 = fmaf(w[i + 1], g4.y, acc1);
            acc0 = fmaf(w[i + 2], g4.z, acc0);
            acc1 = fmaf(w[i + 3], g4.w, acc1);
        }
        #pragma unroll
        for (; i < t; ++i) acc0 = fmaf(w[i], Gr[i], acc0);
        float s = gg * (acc0 + acc1);

        float al = sal[t], be = sbe[t], nn = sn0[t];
        float r2 = fmaxf(fmaf(-2.f, s, q) + nn, 1e-20f);
        float rin = rsqrtf(r2);
        float r = r2 * rin;
        float den = al + r;
        float h = __frcp_rn(den);
        float v = __frcp_rn(den + be);
        float bh = be * h;
        float opbh = 1.f + bh;
        float t2 = opbh - bh * (h * r);
        prod *= t2;
        q = fmaf(bh * bh, r2, fmaf(2.f * bh, q - s, q));
        gg *= opbh;
        gi *= den * v;
        w[t] = -bh * gi;
    }

    g_lp[(size_t)(nbase + tid) * CC + c] = 63.f * __logf(gg) + __logf(prod) - 0.5f * q - 58.8120661251f;
}

// ---- epilogue: warp = sample; 16 samples per block (proven) ----
__global__ void __launch_bounds__(512) out_kernel(const float* __restrict__ x,
                                                  const int* __restrict__ labels,
                                                  const float* __restrict__ freq,
                                                  const float* __restrict__ W,
                                                  const float* __restrict__ b,
                                                  float* __restrict__ out) {
    __shared__ __align__(16) float sWt[CC * 68];
    __shared__ __align__(16) float sxr[16 * 68];
    __shared__ float sb[CC], slf[CC];
    const int tid = threadIdx.x;
    for (int i = tid; i < DD * CC; i += 512) {
        int d = i / CC, cc = i % CC;
        sWt[cc * 68 + d] = W[i];
    }
    for (int i = tid; i < CC; i += 512) { sb[i] = b[i]; slf[i] = __logf(freq[i]); }

    const int wid = tid >> 5, lane = tid & 31;
    const int n = blockIdx.x * 16 + wid;
    {
        const float2* xp = (const float2*)(x + (size_t)n * DD);
        ((float2*)(sxr + wid * 68))[lane] = xp[lane];
    }
    __syncthreads();

    u64 xv[32];
    {
        const ulonglong2* xr = (const ulonglong2*)(sxr + wid * 68);
        #pragma unroll
        for (int j = 0; j < 16; ++j) {
            ulonglong2 v = xr[j];
            xv[2 * j] = v.x; xv[2 * j + 1] = v.y;
        }
    }

    const float* lprow = g_lp + (size_t)n * CC;
    float lg[4], lq[4];
    float mlg = -1e30f, mlp = -1e30f;
    #pragma unroll
    for (int k = 0; k < 4; ++k) {
        int cc = lane + 32 * k;
        if (cc < CC) {
            const ulonglong2* wr = (const ulonglong2*)(sWt + cc * 68);
            u64 a0 = 0ull, a1 = 0ull;
            #pragma unroll
            for (int j = 0; j < 16; ++j) {
                ulonglong2 v = wr[j];
                a0 = fma2(xv[2 * j],     v.x, a0);
                a1 = fma2(xv[2 * j + 1], v.y, a1);
            }
            float2 f = upk2(add2(a0, a1));
            lg[k] = f.x + f.y + sb[cc];
            lq[k] = lprow[cc] + slf[cc];
        } else {
            lg[k] = -1e30f; lq[k] = -1e30f;
        }
        mlg = fmaxf(mlg, lg[k]);
        mlp = fmaxf(mlp, lq[k]);
    }
    #pragma unroll
    for (int o = 16; o; o >>= 1) {
        mlg = fmaxf(mlg, __shfl_xor_sync(0xffffffffu, mlg, o));
        mlp = fmaxf(mlp, __shfl_xor_sync(0xffffffffu, mlp, o));
    }
    float se = 0.f, sl = 0.f;
    #pragma unroll
    for (int k = 0; k < 4; ++k) {
        if (lane + 32 * k < CC) {
            se += __expf(lq[k] - mlp);
            sl += __expf(lg[k] - mlg);
        }
    }
    #pragma unroll
    for (int o = 16; o; o >>= 1) {
        se += __shfl_xor_sync(0xffffffffu, se, o);
        sl += __shfl_xor_sync(0xffffffffu, sl, o);
    }
    float marg = mlp + __logf(se);
    float logev = fminf(marg + 80.992775903f, 10.f);
    float E = __expf(logev) / sl;

    float* o = out + (size_t)n * (CC + 1);
    #pragma unroll
    for (int k = 0; k < 4; ++k) {
        int cc = lane + 32 * k;
        if (cc < CC)
            o[cc] = __logf(fmaf(E, __expf(lg[k] - mlg), 1.f));
    }
    if (lane == 0)
        o[CC] = lprow[labels[n]];
}

extern "C" void kernel_launch(void* const* d_in, const int* in_sizes, int n_in,
                              void* d_out, int out_size) {
    const float* x      = (const float*)d_in[0];
    const int*   labels = (const int*)d_in[1];
    const float* freq   = (const float*)d_in[2];
    const float* z0     = (const float*)d_in[3];
    const float* ap     = (const float*)d_in[4];
    const float* bp     = (const float*)d_in[5];
    const float* W      = (const float*)d_in[6];
    const float* b      = (const float*)d_in[7];
    float* out = (float*)d_out;

    prep_kernel<<<CC, 512>>>(z0, ap, bp);
    dim3 grid(NN / 128, CC);
    flow_kernel<<<grid, 128>>>(x, z0);
    out_kernel<<<NN / 16, 512>>>(x, labels, freq, W, b, out);
}

// round 11
// speedup vs baseline: 1.4641x; 1.0422x over previous
#include <cuda_runtime.h>
#include <math.h>
#include <stdint.h>

#define NN 8192
#define DD 64
#define CC 100
#define TT 30
#define HC 50
#define NPAIR 465

// ---- device-global scratch ----
__device__ float g_lp[NN * CC];
__device__ float g_G[CC * TT * 32];
__device__ float g_al[CC * 32];
__device__ float g_be[CC * 32];
__device__ float g_n0[CC * 32];

typedef unsigned long long u64;

__device__ __forceinline__ float2 upk2(u64 v) {
    float2 f; asm("mov.b64 {%0, %1}, %2;" : "=f"(f.x), "=f"(f.y) : "l"(v)); return f;
}
__device__ __forceinline__ u64 pk2(float lo, float hi) {
    u64 r; asm("mov.b64 %0, {%1, %2};" : "=l"(r) : "f"(lo), "f"(hi)); return r;
}
__device__ __forceinline__ u64 fma2(u64 a, u64 b, u64 c) {
    u64 d; asm("fma.rn.f32x2 %0, %1, %2, %3;" : "=l"(d) : "l"(a), "l"(b), "l"(c)); return d;
}
__device__ __forceinline__ u64 add2(u64 a, u64 b) {
    u64 d; asm("add.rn.f32x2 %0, %1, %2;" : "=l"(d) : "l"(a), "l"(b)); return d;
}

// ---- prep: per-class params + Gram (proven) ----
__global__ void __launch_bounds__(512) prep_kernel(const float* __restrict__ z0,
                                                   const float* __restrict__ ap,
                                                   const float* __restrict__ bp) {
    __shared__ float sz[TT * 65];
    const int tid = threadIdx.x;
    const int c = blockIdx.x;

    for (int i = tid; i < TT * DD; i += 512) {
        int r = i >> 6, col = i & 63;
        sz[r * 65 + col] = z0[(size_t)c * TT * DD + i];
    }
    if (tid < TT) {
        float a  = log1pf(__expf(ap[c * TT + tid]));
        float be = log1pf(__expf(bp[c * TT + tid])) - a;
        g_al[c * 32 + tid] = a;
        g_be[c * 32 + tid] = be;
    }
    __syncthreads();

    int k = tid;
    if (k < NPAIR) {
        int t = (int)((__fsqrt_rn(8.f * k + 1.f) - 1.f) * 0.5f);
        while ((t + 1) * (t + 2) / 2 <= k) ++t;
        while (t * (t + 1) / 2 > k) --t;
        int i = k - t * (t + 1) / 2;
        const float* za = sz + t * 65;
        const float* zb = sz + i * 65;
        float a0 = 0.f, a1 = 0.f, a2 = 0.f, a3 = 0.f;
        #pragma unroll
        for (int d = 0; d < DD; d += 4) {
            a0 = fmaf(za[d],     zb[d],     a0);
            a1 = fmaf(za[d + 1], zb[d + 1], a1);
            a2 = fmaf(za[d + 2], zb[d + 2], a2);
            a3 = fmaf(za[d + 3], zb[d + 3], a3);
        }
        float dot = (a0 + a1) + (a2 + a3);
        if (i == t) g_n0[c * 32 + t] = dot;
        else        g_G[(size_t)c * TT * 32 + t * 32 + i] = dot;
    }
}

__device__ __forceinline__ void mma_tf32(float& c0, float& c1, float& c2, float& c3,
                                         uint32_t a0, uint32_t a1, uint32_t a2, uint32_t a3,
                                         uint32_t b0, uint32_t b1) {
    asm volatile(
        "mma.sync.aligned.m16n8k8.row.col.f32.tf32.tf32.f32 "
        "{%0,%1,%2,%3}, {%4,%5,%6,%7}, {%8,%9}, {%0,%1,%2,%3};"
        : "+f"(c0), "+f"(c1), "+f"(c2), "+f"(c3)
        : "r"(a0), "r"(a1), "r"(a2), "r"(a3), "r"(b0), "r"(b1));
}

// dynamic smem layout (float indices):
//  buf [0, 8704)        x tile 128 x 68; aliased by sp (u64, 128 x 33 = 8448 floats)
//  sz  [8704, 13056)    two z0 tiles (32 x 68 each)
//  sG2 [13056, 14976)   paired Gram (u64[960])
//  prm [14976, 15168)   {al,be,n0} x 2 classes
#define OFF_Z   8704
#define OFF_G2  13056
#define OFF_PRM 14976
#define SMEM_FLOATS 15168
#define SMEM_BYTES (SMEM_FLOATS * 4)

// ---- flow: block = 128 samples x 2 classes; tf32 mma + packed dual chain ----
__global__ void __launch_bounds__(128, 3) flow_kernel(const float* __restrict__ x,
                                                      const float* __restrict__ z0g) {
    extern __shared__ __align__(16) float sm[];
    float* sx   = sm;
    float* szz  = sm + OFF_Z;
    u64*   sG2  = (u64*)(sm + OFF_G2);
    float* prmA = sm + OFF_PRM;        // al@0 be@32 n0@64
    float* prmB = sm + OFF_PRM + 96;

    const int tid = threadIdx.x;
    const int wid = tid >> 5;
    const int lane = tid & 31;
    const int g = lane >> 2;
    const int cc4 = lane & 3;
    const int c0 = blockIdx.y;
    const int c1 = blockIdx.y + HC;
    const int nbase = blockIdx.x * 128;

    // stage x tile (pitch 17 float4)
    {
        const float4* gx = (const float4*)(x + (size_t)nbase * DD);
        float4* s4 = (float4*)sx;
        #pragma unroll
        for (int j = 0; j < 16; ++j) {
            int idx = tid + 128 * j;
            int r = idx >> 4, col = idx & 15;
            s4[r * 17 + col] = gx[idx];
        }
    }
    // stage both z0 tiles (32 x 68, rows 30/31 zero)
    {
        const float* gz0 = z0g + (size_t)c0 * TT * DD;
        const float* gz1 = z0g + (size_t)c1 * TT * DD;
        #pragma unroll
        for (int i = tid; i < 4096; i += 128) {
            int cls = i >> 11;
            int ii = i & 2047;
            int r = ii >> 6, col = ii & 63;
            const float* gz = cls ? gz1 : gz0;
            szz[cls * 2176 + r * 68 + col] = (ii < 1920) ? gz[ii] : 0.f;
        }
    }
    // paired Gram
    {
        const float* GA = g_G + (size_t)c0 * TT * 32;
        const float* GB = g_G + (size_t)c1 * TT * 32;
        #pragma unroll
        for (int k = tid; k < 960; k += 128) sG2[k] = pk2(GA[k], GB[k]);
    }
    // params
    if (tid < 64) {
        int cls = tid >> 5, t = tid & 31;
        int c = cls ? c1 : c0;
        float* p = cls ? prmB : prmA;
        p[t]      = g_al[c * 32 + t];
        p[32 + t] = g_be[c * 32 + t];
        p[64 + t] = g_n0[c * 32 + t];
    }
    __syncthreads();

    // q0 = ||x||^2 (own row)
    float q0;
    {
        const float4* xr = ((const float4*)sx) + tid * 17;
        float a0 = 0.f, a1 = 0.f, a2 = 0.f, a3 = 0.f;
        #pragma unroll
        for (int j = 0; j < 16; ++j) {
            float4 v = xr[j];
            a0 = fmaf(v.x, v.x, a0);
            a1 = fmaf(v.y, v.y, a1);
            a2 = fmaf(v.z, v.z, a2);
            a3 = fmaf(v.w, v.w, a3);
        }
        q0 = (a0 + a1) + (a2 + a3);
    }

    // ---- MMA: P[32 samples x 32 ts] per warp, both classes ----
    float CA[2][4][4], CB[2][4][4];
    #pragma unroll
    for (int mt = 0; mt < 2; ++mt)
        #pragma unroll
        for (int nt = 0; nt < 4; ++nt)
            #pragma unroll
            for (int r = 0; r < 4; ++r) { CA[mt][nt][r] = 0.f; CB[mt][nt][r] = 0.f; }

    const uint32_t* xa  = (const uint32_t*)(sx + (32 * wid + g) * 68);
    const uint32_t* zbA = (const uint32_t*)(szz + g * 68);
    const uint32_t* zbB = (const uint32_t*)(szz + 2176 + g * 68);

    #pragma unroll
    for (int ks = 0; ks < 8; ++ks) {
        int k0 = 8 * ks + cc4;
        uint32_t a00 = xa[k0],               a01 = xa[8 * 68 + k0];
        uint32_t a02 = xa[k0 + 4],           a03 = xa[8 * 68 + k0 + 4];
        uint32_t a10 = xa[16 * 68 + k0],     a11 = xa[24 * 68 + k0];
        uint32_t a12 = xa[16 * 68 + k0 + 4], a13 = xa[24 * 68 + k0 + 4];
        #pragma unroll
        for (int nt = 0; nt < 4; ++nt) {
            uint32_t bA0 = zbA[nt * 8 * 68 + k0];
            uint32_t bA1 = zbA[nt * 8 * 68 + k0 + 4];
            mma_tf32(CA[0][nt][0], CA[0][nt][1], CA[0][nt][2], CA[0][nt][3],
                     a00, a01, a02, a03, bA0, bA1);
            mma_tf32(CA[1][nt][0], CA[1][nt][1], CA[1][nt][2], CA[1][nt][3],
                     a10, a11, a12, a13, bA0, bA1);
            uint32_t bB0 = zbB[nt * 8 * 68 + k0];
            uint32_t bB1 = zbB[nt * 8 * 68 + k0 + 4];
            mma_tf32(CB[0][nt][0], CB[0][nt][1], CB[0][nt][2], CB[0][nt][3],
                     a00, a01, a02, a03, bB0, bB1);
            mma_tf32(CB[1][nt][0], CB[1][nt][1], CB[1][nt][2], CB[1][nt][3],
                     a10, a11, a12, a13, bB0, bB1);
        }
    }
    __syncthreads();   // x tile reads done -> alias sp

    // write paired P: spq[s*33 + t] = {pA, pB}
    u64* spq = (u64*)sx;
    #pragma unroll
    for (int mt = 0; mt < 2; ++mt) {
        #pragma unroll
        for (int nt = 0; nt < 4; ++nt) {
            int s0 = 32 * wid + mt * 16 + g;
            int t0 = nt * 8 + 2 * cc4;
            spq[s0 * 33 + t0]           = pk2(CA[mt][nt][0], CB[mt][nt][0]);
            spq[s0 * 33 + t0 + 1]       = pk2(CA[mt][nt][1], CB[mt][nt][1]);
            spq[(s0 + 8) * 33 + t0]     = pk2(CA[mt][nt][2], CB[mt][nt][2]);
            spq[(s0 + 8) * 33 + t0 + 1] = pk2(CA[mt][nt][3], CB[mt][nt][3]);
        }
    }
    __syncwarp();

    // ---- packed dual-class chain ----
    u64 wp[TT];
    float qA = q0, qB = q0;
    float gA = 1.f, gB = 1.f, giA = 1.f, giB = 1.f, prodA = 1.f, prodB = 1.f;

    #pragma unroll
    for (int t = 0; t < TT; ++t) {
        const u64* G2 = sG2 + t * 32;
        u64 acc0 = 0ull, acc1 = 0ull;
        int i = 0;
        #pragma unroll
        for (; i + 2 <= t; i += 2) {
            ulonglong2 gq = *(const ulonglong2*)(G2 + i);
            acc0 = fma2(wp[i],     gq.x, acc0);
            acc1 = fma2(wp[i + 1], gq.y, acc1);
        }
        if (i < t) acc0 = fma2(wp[i], G2[i], acc0);
        float2 dot = upk2(add2(add2(acc0, acc1), spq[tid * 33 + t]));

        float sA = gA * dot.x;
        float sB = gB * dot.y;

        float alA = prmA[t], beA = prmA[32 + t], nnA = prmA[64 + t];
        float alB = prmB[t], beB = prmB[32 + t], nnB = prmB[64 + t];

        float r2A = fmaxf(fmaf(-2.f, sA, qA) + nnA, 1e-20f);
        float r2B = fmaxf(fmaf(-2.f, sB, qB) + nnB, 1e-20f);
        float rinA = rsqrtf(r2A), rinB = rsqrtf(r2B);
        float rA = r2A * rinA,    rB = r2B * rinB;
        float dA = alA + rA,      dB = alB + rB;
        float hA = __frcp_rn(dA),        hB = __frcp_rn(dB);
        float vA = __frcp_rn(dA + beA),  vB = __frcp_rn(dB + beB);
        float bhA = beA * hA,     bhB = beB * hB;
        float opA = 1.f + bhA,    opB = 1.f + bhB;
        float t2A = opA - bhA * (hA * rA);
        float t2B = opB - bhB * (hB * rB);
        prodA *= t2A;             prodB *= t2B;
        qA = fmaf(bhA * bhA, r2A, fmaf(2.f * bhA, qA - sA, qA));
        qB = fmaf(bhB * bhB, r2B, fmaf(2.f * bhB, qB - sB, qB));
        gA *= opA;                gB *= opB;
        giA *= dA * vA;           giB *= dB * vB;
        wp[t] = pk2(-bhA * giA, -bhB * giB);
    }

    float lpA = 63.f * __logf(gA) + __logf(prodA) - 0.5f * qA - 58.8120661251f;
    float lpB = 63.f * __logf(gB) + __logf(prodB) - 0.5f * qB - 58.8120661251f;
    g_lp[(size_t)(nbase + tid) * CC + c0] = lpA;
    g_lp[(size_t)(nbase + tid) * CC + c1] = lpB;
}

// ---- epilogue: warp = sample; 16 samples per block (proven) ----
__global__ void __launch_bounds__(512) out_kernel(const float* __restrict__ x,
                                                  const int* __restrict__ labels,
                                                  const float* __restrict__ freq,
                                                  const float* __restrict__ W,
                                                  const float* __restrict__ b,
                                                  float* __restrict__ out) {
    __shared__ __align__(16) float sWt[CC * 68];
    __shared__ __align__(16) float sxr[16 * 68];
    __shared__ float sb[CC], slf[CC];
    const int tid = threadIdx.x;
    for (int i = tid; i < DD * CC; i += 512) {
        int d = i / CC, cc = i % CC;
        sWt[cc * 68 + d] = W[i];
    }
    for (int i = tid; i < CC; i += 512) { sb[i] = b[i]; slf[i] = __logf(freq[i]); }

    const int wid = tid >> 5, lane = tid & 31;
    const int n = blockIdx.x * 16 + wid;
    {
        const float2* xp = (const float2*)(x + (size_t)n * DD);
        ((float2*)(sxr + wid * 68))[lane] = xp[lane];
    }
    __syncthreads();

    u64 xv[32];
    {
        const ulonglong2* xr = (const ulonglong2*)(sxr + wid * 68);
        #pragma unroll
        for (int j = 0; j < 16; ++j) {
            ulonglong2 v = xr[j];
            xv[2 * j] = v.x; xv[2 * j + 1] = v.y;
        }
    }

    const float* lprow = g_lp + (size_t)n * CC;
    float lg[4], lq[4];
    float mlg = -1e30f, mlp = -1e30f;
    #pragma unroll
    for (int k = 0; k < 4; ++k) {
        int cc = lane + 32 * k;
        if (cc < CC) {
            const ulonglong2* wr = (const ulonglong2*)(sWt + cc * 68);
            u64 a0 = 0ull, a1 = 0ull;
            #pragma unroll
            for (int j = 0; j < 16; ++j) {
                ulonglong2 v = wr[j];
                a0 = fma2(xv[2 * j],     v.x, a0);
                a1 = fma2(xv[2 * j + 1], v.y, a1);
            }
            float2 f = upk2(add2(a0, a1));
            lg[k] = f.x + f.y + sb[cc];
            lq[k] = lprow[cc] + slf[cc];
        } else {
            lg[k] = -1e30f; lq[k] = -1e30f;
        }
        mlg = fmaxf(mlg, lg[k]);
        mlp = fmaxf(mlp, lq[k]);
    }
    #pragma unroll
    for (int o = 16; o; o >>= 1) {
        mlg = fmaxf(mlg, __shfl_xor_sync(0xffffffffu, mlg, o));
        mlp = fmaxf(mlp, __shfl_xor_sync(0xffffffffu, mlp, o));
    }
    float se = 0.f, sl = 0.f;
    #pragma unroll
    for (int k = 0; k < 4; ++k) {
        if (lane + 32 * k < CC) {
            se += __expf(lq[k] - mlp);
            sl += __expf(lg[k] - mlg);
        }
    }
    #pragma unroll
    for (int o = 16; o; o >>= 1) {
        se += __shfl_xor_sync(0xffffffffu, se, o);
        sl += __shfl_xor_sync(0xffffffffu, sl, o);
    }
    float marg = mlp + __logf(se);
    float logev = fminf(marg + 80.992775903f, 10.f);
    float E = __expf(logev) / sl;

    float* o = out + (size_t)n * (CC + 1);
    #pragma unroll
    for (int k = 0; k < 4; ++k) {
        int cc = lane + 32 * k;
        if (cc < CC)
            o[cc] = __logf(fmaf(E, __expf(lg[k] - mlg), 1.f));
    }
    if (lane == 0)
        o[CC] = lprow[labels[n]];
}

extern "C" void kernel_launch(void* const* d_in, const int* in_sizes, int n_in,
                              void* d_out, int out_size) {
    const float* x      = (const float*)d_in[0];
    const int*   labels = (const int*)d_in[1];
    const float* freq   = (const float*)d_in[2];
    const float* z0     = (const float*)d_in[3];
    const float* ap     = (const float*)d_in[4];
    const float* bp     = (const float*)d_in[5];
    const float* W      = (const float*)d_in[6];
    const float* b      = (const float*)d_in[7];
    float* out = (float*)d_out;

    cudaFuncSetAttribute(flow_kernel, cudaFuncAttributeMaxDynamicSharedMemorySize, SMEM_BYTES);

    prep_kernel<<<CC, 512>>>(z0, ap, bp);
    dim3 grid(NN / 128, HC);
    flow_kernel<<<grid, 128, SMEM_BYTES>>>(x, z0);
    out_kernel<<<NN / 16, 512>>>(x, labels, freq, W, b, out);
}